// round 4
// baseline (speedup 1.0000x reference)
#include <cuda_runtime.h>
#include <math.h>

#define Bsz 1024
#define Ssz 350
#define Vsz 41
#define BT 8
#define NCTA 128
#define NTHR 768

typedef unsigned long long u64;

// ---------------- persistent device scratch ----------------
__device__ float4 g_A[49152];      // Whh0 e-pair packed: [kc][gate*256 + c2*128 + j]
__device__ float4 g_B1rz[16384];   // Wih1 (r,z) pairs: [kc][c2*128 + j]
__device__ float4 g_B1n[8192];     // Wih1 n rows: [kc][j] = 4 k
__device__ float4 g_B2rz[8192];    // Whh1 (r,z)
__device__ float4 g_B2n[4096];
__device__ float4 g_C1rz[2048];    // Wih2
__device__ float4 g_C1n[1024];
__device__ float4 g_C2rz[512];     // Whh2
__device__ float4 g_C2n[256];
__device__ float  g_WprojT[1312];  // [k][j]
__device__ float  g_G0x[41 * 768]; // [v][gate][jm] -> (col jm, col jm+128) pairs
__device__ float  g_Hinit[Bsz * 416];

// ---------------- f32x2 helpers ----------------
__device__ __forceinline__ u64 fma2(u64 a, u64 b, u64 c) {
    u64 d; asm("fma.rn.f32x2 %0,%1,%2,%3;" : "=l"(d) : "l"(a), "l"(b), "l"(c)); return d;
}
__device__ __forceinline__ u64 add2(u64 a, u64 b) {
    u64 d; asm("add.rn.f32x2 %0,%1,%2;" : "=l"(d) : "l"(a), "l"(b)); return d;
}
__device__ __forceinline__ u64 pk2(float x, float y) {
    u64 d; asm("mov.b64 %0,{%1,%2};" : "=l"(d) : "f"(x), "f"(y)); return d;
}
__device__ __forceinline__ void up2(u64 a, float& x, float& y) {
    asm("mov.b64 {%0,%1}, %2;" : "=f"(x), "=f"(y) : "l"(a));
}
__device__ __forceinline__ float lo2(u64 a) { float x, y; up2(a, x, y); return x; }

__device__ __forceinline__ float sigf(float x) {
    return __fdividef(1.0f, 1.0f + __expf(-x));
}
__device__ __forceinline__ float tanh_(float x) {
    float ax = fabsf(x);
    float e = __expf(-2.0f * ax);
    float t = __fdividef(1.0f - e, 1.0f + e);
    return copysignf(t, x);
}

// ---------------- fused prep kernel (unchanged) ----------------
__global__ void k_prep(const float* __restrict__ latent, const float* __restrict__ W_emb,
                       const float* __restrict__ b_emb, const float* __restrict__ W_init,
                       const float* __restrict__ b_init, const float* __restrict__ Wih0,
                       const float* __restrict__ bih0, const float* __restrict__ Whh0,
                       const float* __restrict__ Wih1, const float* __restrict__ Whh1,
                       const float* __restrict__ Wih2, const float* __restrict__ Whh2,
                       const float* __restrict__ W_proj) {
    const int b = blockIdx.x, tid = threadIdx.x;
    const int PTH = 256;
    if (b < 128) {
        __shared__ float lat[8 * 512];
        const int b0 = b * 8;
        for (int i = tid; i < 8 * 512; i += PTH) lat[i] = latent[(size_t)b0 * 512 + i];
        __syncthreads();
        for (int c = tid; c < 416; c += PTH) {
            float acc[8];
            float bi = b_init[c];
#pragma unroll
            for (int r = 0; r < 8; r++) acc[r] = bi;
            const float* w = W_init + (size_t)c * 512;
            for (int k = 0; k < 512; k += 4) {
                float4 wv = *(const float4*)(w + k);
#pragma unroll
                for (int r = 0; r < 8; r++) {
                    acc[r] += wv.x * lat[r * 512 + k];
                    acc[r] += wv.y * lat[r * 512 + k + 1];
                    acc[r] += wv.z * lat[r * 512 + k + 2];
                    acc[r] += wv.w * lat[r * 512 + k + 3];
                }
            }
#pragma unroll
            for (int r = 0; r < 8; r++) g_Hinit[(size_t)(b0 + r) * 416 + c] = acc[r];
        }
    } else if (b < 169) {
        const int v = b - 128;
        __shared__ float emb[512];
        for (int k = tid; k < 512; k += PTH) emb[k] = W_emb[k * Vsz + v] + b_emb[k];
        __syncthreads();
        for (int j = tid; j < 768; j += PTH) {
            float acc = bih0[j];
            const float* w = Wih0 + (size_t)j * 512;
            for (int k = 0; k < 512; k += 4) {
                float4 wv = *(const float4*)(w + k);
                acc += wv.x * emb[k] + wv.y * emb[k + 1] + wv.z * emb[k + 2] + wv.w * emb[k + 3];
            }
            int g = j >> 8, rem = j & 255, e = rem >> 7, jm = rem & 127;
            g_G0x[(((size_t)v * 3 + g) * 128 + jm) * 2 + e] = acc;
        }
    } else {
        const int TOTAL = 90184;
        for (int i = (b - 169) * PTH + tid; i < TOTAL; i += 87 * PTH) {
            if (i < 49152) {
                int kc = i / 768, rem = i % 768;
                int g = rem / 256, rem2 = rem % 256, c2 = rem2 >> 7, jj = rem2 & 127;
                int k = 4 * kc + 2 * c2, row0 = g * 256 + jj, row1 = row0 + 128;
                g_A[i] = make_float4(Whh0[row0 * 256 + k], Whh0[row1 * 256 + k],
                                     Whh0[row0 * 256 + k + 1], Whh0[row1 * 256 + k + 1]);
            } else if (i < 65536) {
                int t = i - 49152;
                int kc = t / 256, c2 = (t & 255) >> 7, jj = t & 127, k = 4 * kc + 2 * c2;
                g_B1rz[t] = make_float4(Wih1[jj * 256 + k], Wih1[(128 + jj) * 256 + k],
                                        Wih1[jj * 256 + k + 1], Wih1[(128 + jj) * 256 + k + 1]);
            } else if (i < 73728) {
                int t = i - 65536;
                int kc = t >> 7, jj = t & 127;
                g_B1n[t] = *(const float4*)&Wih1[(256 + jj) * 256 + 4 * kc];
            } else if (i < 81920) {
                int t = i - 73728;
                int kc = t / 256, c2 = (t & 255) >> 7, jj = t & 127, k = 4 * kc + 2 * c2;
                g_B2rz[t] = make_float4(Whh1[jj * 128 + k], Whh1[(128 + jj) * 128 + k],
                                        Whh1[jj * 128 + k + 1], Whh1[(128 + jj) * 128 + k + 1]);
            } else if (i < 86016) {
                int t = i - 81920;
                int kc = t >> 7, jj = t & 127;
                g_B2n[t] = *(const float4*)&Whh1[(256 + jj) * 128 + 4 * kc];
            } else if (i < 88064) {
                int t = i - 86016;
                int kc = t / 64, c2 = (t & 63) >> 5, jc = t & 31, k = 4 * kc + 2 * c2;
                g_C1rz[t] = make_float4(Wih2[jc * 128 + k], Wih2[(32 + jc) * 128 + k],
                                        Wih2[jc * 128 + k + 1], Wih2[(32 + jc) * 128 + k + 1]);
            } else if (i < 89088) {
                int t = i - 88064;
                int kc = t >> 5, jc = t & 31;
                g_C1n[t] = *(const float4*)&Wih2[(64 + jc) * 128 + 4 * kc];
            } else if (i < 89600) {
                int t = i - 89088;
                int kc = t / 64, c2 = (t & 63) >> 5, jc = t & 31, k = 4 * kc + 2 * c2;
                g_C2rz[t] = make_float4(Whh2[jc * 32 + k], Whh2[(32 + jc) * 32 + k],
                                        Whh2[jc * 32 + k + 1], Whh2[(32 + jc) * 32 + k + 1]);
            } else if (i < 89856) {
                int t = i - 89600;
                int kc = t >> 5, jc = t & 31;
                g_C2n[t] = *(const float4*)&Whh2[(64 + jc) * 32 + 4 * kc];
            } else {
                int t2 = i - 89856;
#pragma unroll
                for (int c = 0; c < 4; c++) {
                    int e = t2 * 4 + c;
                    if (e < 1312) {
                        int k = e / Vsz, j = e - k * Vsz;
                        g_WprojT[e] = W_proj[j * 32 + k];
                    }
                }
            }
        }
    }
}

// dynamic smem layout (bytes)
#define SM_H0   0
#define SM_H1   16384
#define SM_H2   24576
#define SM_CMB  26624
#define SM_TOK  51200
#define SM_LG   62400
#define SM_TOTAL 63808

// ---------------- main persistent GRU kernel ----------------
__global__ __launch_bounds__(NTHR, 1)
void k_main(const int* __restrict__ tokens,
            const float* __restrict__ bhh0,
            const float* __restrict__ bih1, const float* __restrict__ bhh1,
            const float* __restrict__ bih2, const float* __restrict__ bhh2,
            const float* __restrict__ b_proj,
            float* __restrict__ out, float* __restrict__ pred) {
    extern __shared__ __align__(16) char smraw[];
    u64* h0d = (u64*)(smraw + SM_H0);        // [256 cols][8 rows] dup pairs
    u64* h1d = (u64*)(smraw + SM_H1);        // [128][8]
    u64* h2d = (u64*)(smraw + SM_H2);        // [32][8]
    u64* cmb = (u64*)(smraw + SM_CMB);       // [3][4][256]
    int* toksAll = (int*)(smraw + SM_TOK);   // [350][8]
    float* lg = (float*)(smraw + SM_LG);     // [8][44]

    const int tid = threadIdx.x;
    const int b0 = blockIdx.x * BT;
    const int g3 = tid >> 8;          // gate group 0..2
    const int tA = tid & 255;
    const int jj = tA & 127;
    const int r0 = (tA >> 7) * 4;
    const int jc = tA & 31;
    const int rowC = tA >> 5;

    // tokens preload (SOS at step 0)
    for (int i = tid; i < Ssz * 8; i += NTHR) {
        int stt = i >> 3, row = i & 7;
        toksAll[i] = (stt == 0) ? 1 : tokens[(size_t)(b0 + row) * Ssz + stt];
    }

    // initial state -> dup smem
    for (int idx = tid; idx < BT * 416; idx += NTHR) {
        int row = idx / 416, c = idx - row * 416;
        float v = g_Hinit[(size_t)(b0 + row) * 416 + c];
        if (c < 256)      h0d[c * 8 + row] = pk2(v, v);
        else if (c < 384) h1d[(c - 256) * 8 + row] = pk2(v, v);
        else              h2d[(c - 384) * 8 + row] = pk2(v, v);
    }

    // role biases
    const u64 bA = pk2(bhh0[g3 * 256 + jj], bhh0[g3 * 256 + 128 + jj]);
    u64 bB, bC;
    if (g3 == 0) {
        bB = pk2(bih1[jj] + bhh1[jj], bih1[128 + jj] + bhh1[128 + jj]);
        bC = pk2(bih2[jc] + bhh2[jc], bih2[32 + jc] + bhh2[32 + jc]);
    } else if (g3 == 1) {
        float t = bih1[256 + jj]; bB = pk2(t, t);
        float t2 = bih2[64 + jc]; bC = pk2(t2, t2);
    } else {
        float t = bhh1[256 + jj]; bB = pk2(t, t);
        float t2 = bhh2[64 + jc]; bC = pk2(t2, t2);
    }

    const u64* __restrict__ G0p = (const u64*)g_G0x;

    __syncthreads();

    for (int st = 0; st < Ssz; st++) {
        const int* tokrow = toksAll + st * 8;

        // ======== Phase A accum: one gate per group, 1-deep weight prefetch ========
        {
            u64 acc[4];
            if (g3 < 2) {
#pragma unroll
                for (int r = 0; r < 4; r++)
                    acc[r] = add2(G0p[(size_t)tokrow[r0 + r] * 384 + g3 * 128 + jj], bA);
            } else {
#pragma unroll
                for (int r = 0; r < 4; r++) acc[r] = bA;
            }
            const float4* gb = g_A + g3 * 256 + jj;
            ulonglong2 cw0 = *(const ulonglong2*)gb;
            ulonglong2 cw1 = *(const ulonglong2*)(gb + 128);
#pragma unroll 2
            for (int kc = 0; kc < 64; kc++) {
                int nkc = (kc < 63) ? kc + 1 : 63;
                ulonglong2 nw0 = *(const ulonglong2*)(gb + nkc * 768);
                ulonglong2 nw1 = *(const ulonglong2*)(gb + nkc * 768 + 128);
                u64 W[4] = {cw0.x, cw0.y, cw1.x, cw1.y};
                u64 hv[4][4];
#pragma unroll
                for (int c = 0; c < 4; c++) {
                    ulonglong2 ha = *(const ulonglong2*)&h0d[(4 * kc + c) * 8 + r0];
                    ulonglong2 hb = *(const ulonglong2*)&h0d[(4 * kc + c) * 8 + r0 + 2];
                    hv[c][0] = ha.x; hv[c][1] = ha.y; hv[c][2] = hb.x; hv[c][3] = hb.y;
                }
#pragma unroll
                for (int c = 0; c < 4; c++)
#pragma unroll
                    for (int r = 0; r < 4; r++) acc[r] = fma2(W[c], hv[c][r], acc[r]);
                cw0 = nw0; cw1 = nw1;
            }
#pragma unroll
            for (int r = 0; r < 4; r++) cmb[g3 * 1024 + r * 256 + tA] = acc[r];
        }
        __syncthreads();

        // ======== Phase A elementwise: all threads ========
        for (int q = tid; q < 1024; q += NTHR) {
            int jm = q & 127, row = q >> 7;
            int rh = row >> 2, rr = row & 3;
            int ta = (rh << 7) + jm;
            u64 aR = cmb[rr * 256 + ta];
            u64 aZ = cmb[1024 + rr * 256 + ta];
            u64 aN = cmb[2048 + rr * 256 + ta];
            u64 gIN = G0p[(size_t)tokrow[row] * 384 + 256 + jm];
            float r0e, r1e, z0e, z1e, n0e, n1e, i0e, i1e;
            up2(aR, r0e, r1e); up2(aZ, z0e, z1e);
            up2(aN, n0e, n1e); up2(gIN, i0e, i1e);
            float hold0 = lo2(h0d[jm * 8 + row]);
            float hold1 = lo2(h0d[(128 + jm) * 8 + row]);
            float rg0 = sigf(r0e), rg1 = sigf(r1e);
            float zg0 = sigf(z0e), zg1 = sigf(z1e);
            float ng0 = tanh_(i0e + rg0 * n0e), ng1 = tanh_(i1e + rg1 * n1e);
            float v0 = (1.0f - zg0) * ng0 + zg0 * hold0;
            float v1 = (1.0f - zg1) * ng1 + zg1 * hold1;
            h0d[jm * 8 + row] = pk2(v0, v0);
            h0d[(128 + jm) * 8 + row] = pk2(v1, v1);
        }
        __syncthreads();

        // ======== Phase B accum: g0=rz, g1=iN, g2=hN ========
        {
            u64 acc[4];
#pragma unroll
            for (int r = 0; r < 4; r++) acc[r] = bB;
            if (g3 == 0) {
                const float4* gb = g_B1rz + jj;
                ulonglong2 cw0 = *(const ulonglong2*)gb;
                ulonglong2 cw1 = *(const ulonglong2*)(gb + 128);
#pragma unroll 2
                for (int kc = 0; kc < 64; kc++) {
                    int nkc = (kc < 63) ? kc + 1 : 63;
                    ulonglong2 nw0 = *(const ulonglong2*)(gb + nkc * 256);
                    ulonglong2 nw1 = *(const ulonglong2*)(gb + nkc * 256 + 128);
                    u64 W[4] = {cw0.x, cw0.y, cw1.x, cw1.y};
                    u64 hv[4][4];
#pragma unroll
                    for (int c = 0; c < 4; c++) {
                        ulonglong2 ha = *(const ulonglong2*)&h0d[(4 * kc + c) * 8 + r0];
                        ulonglong2 hb = *(const ulonglong2*)&h0d[(4 * kc + c) * 8 + r0 + 2];
                        hv[c][0] = ha.x; hv[c][1] = ha.y; hv[c][2] = hb.x; hv[c][3] = hb.y;
                    }
#pragma unroll
                    for (int c = 0; c < 4; c++)
#pragma unroll
                        for (int r = 0; r < 4; r++) acc[r] = fma2(W[c], hv[c][r], acc[r]);
                    cw0 = nw0; cw1 = nw1;
                }
                const float4* gb2 = g_B2rz + jj;
                ulonglong2 dw0 = *(const ulonglong2*)gb2;
                ulonglong2 dw1 = *(const ulonglong2*)(gb2 + 128);
#pragma unroll 2
                for (int kc = 0; kc < 32; kc++) {
                    int nkc = (kc < 31) ? kc + 1 : 31;
                    ulonglong2 nw0 = *(const ulonglong2*)(gb2 + nkc * 256);
                    ulonglong2 nw1 = *(const ulonglong2*)(gb2 + nkc * 256 + 128);
                    u64 W[4] = {dw0.x, dw0.y, dw1.x, dw1.y};
                    u64 hv[4][4];
#pragma unroll
                    for (int c = 0; c < 4; c++) {
                        ulonglong2 ha = *(const ulonglong2*)&h1d[(4 * kc + c) * 8 + r0];
                        ulonglong2 hb = *(const ulonglong2*)&h1d[(4 * kc + c) * 8 + r0 + 2];
                        hv[c][0] = ha.x; hv[c][1] = ha.y; hv[c][2] = hb.x; hv[c][3] = hb.y;
                    }
#pragma unroll
                    for (int c = 0; c < 4; c++)
#pragma unroll
                        for (int r = 0; r < 4; r++) acc[r] = fma2(W[c], hv[c][r], acc[r]);
                    dw0 = nw0; dw1 = nw1;
                }
            } else if (g3 == 1) {
                const float4* gb = g_B1n + jj;
                float4 cw = *gb;
#pragma unroll 2
                for (int kc = 0; kc < 64; kc++) {
                    int nkc = (kc < 63) ? kc + 1 : 63;
                    float4 nw = *(gb + nkc * 128);
                    u64 W[4] = {pk2(cw.x, cw.x), pk2(cw.y, cw.y),
                                pk2(cw.z, cw.z), pk2(cw.w, cw.w)};
                    u64 hv[4][4];
#pragma unroll
                    for (int c = 0; c < 4; c++) {
                        ulonglong2 ha = *(const ulonglong2*)&h0d[(4 * kc + c) * 8 + r0];
                        ulonglong2 hb = *(const ulonglong2*)&h0d[(4 * kc + c) * 8 + r0 + 2];
                        hv[c][0] = ha.x; hv[c][1] = ha.y; hv[c][2] = hb.x; hv[c][3] = hb.y;
                    }
#pragma unroll
                    for (int c = 0; c < 4; c++)
#pragma unroll
                        for (int r = 0; r < 4; r++) acc[r] = fma2(W[c], hv[c][r], acc[r]);
                    cw = nw;
                }
            } else {
                const float4* gb = g_B2n + jj;
                float4 cw = *gb;
#pragma unroll 2
                for (int kc = 0; kc < 32; kc++) {
                    int nkc = (kc < 31) ? kc + 1 : 31;
                    float4 nw = *(gb + nkc * 128);
                    u64 W[4] = {pk2(cw.x, cw.x), pk2(cw.y, cw.y),
                                pk2(cw.z, cw.z), pk2(cw.w, cw.w)};
                    u64 hv[4][4];
#pragma unroll
                    for (int c = 0; c < 4; c++) {
                        ulonglong2 ha = *(const ulonglong2*)&h1d[(4 * kc + c) * 8 + r0];
                        ulonglong2 hb = *(const ulonglong2*)&h1d[(4 * kc + c) * 8 + r0 + 2];
                        hv[c][0] = ha.x; hv[c][1] = ha.y; hv[c][2] = hb.x; hv[c][3] = hb.y;
                    }
#pragma unroll
                    for (int c = 0; c < 4; c++)
#pragma unroll
                        for (int r = 0; r < 4; r++) acc[r] = fma2(W[c], hv[c][r], acc[r]);
                    cw = nw;
                }
            }
#pragma unroll
            for (int r = 0; r < 4; r++) cmb[g3 * 1024 + r * 256 + tA] = acc[r];
        }
        __syncthreads();

        // ======== Phase B elementwise: all threads ========
        for (int q = tid; q < 1024; q += NTHR) {
            int jm = q & 127, row = q >> 7;
            int rh = row >> 2, rr = row & 3;
            int ta = (rh << 7) + jm;
            u64 rzv = cmb[rr * 256 + ta];
            u64 iN = cmb[1024 + rr * 256 + ta];
            u64 hN = cmb[2048 + rr * 256 + ta];
            float ar, az;
            up2(rzv, ar, az);
            float hold = lo2(h1d[jm * 8 + row]);
            float rg = sigf(ar), zg = sigf(az);
            float ng = tanh_(lo2(iN) + rg * lo2(hN));
            float v = (1.0f - zg) * ng + zg * hold;
            h1d[jm * 8 + row] = pk2(v, v);
        }
        __syncthreads();

        // ======== Phase C accum: g0=rz, g1=iN, g2=hN ========
        {
            u64 acc = bC;
            if (g3 == 0) {
#pragma unroll 2
                for (int kc = 0; kc < 32; kc++) {
                    const float4* brz = g_C1rz + kc * 64;
                    ulonglong2 w01 = *(const ulonglong2*)(brz + jc);
                    ulonglong2 w23 = *(const ulonglong2*)(brz + 32 + jc);
                    u64 W[4] = {w01.x, w01.y, w23.x, w23.y};
#pragma unroll
                    for (int c = 0; c < 4; c++)
                        acc = fma2(W[c], h1d[(4 * kc + c) * 8 + rowC], acc);
                }
#pragma unroll 2
                for (int kc = 0; kc < 8; kc++) {
                    const float4* brz = g_C2rz + kc * 64;
                    ulonglong2 w01 = *(const ulonglong2*)(brz + jc);
                    ulonglong2 w23 = *(const ulonglong2*)(brz + 32 + jc);
                    u64 W[4] = {w01.x, w01.y, w23.x, w23.y};
#pragma unroll
                    for (int c = 0; c < 4; c++)
                        acc = fma2(W[c], h2d[(4 * kc + c) * 8 + rowC], acc);
                }
            } else if (g3 == 1) {
#pragma unroll 2
                for (int kc = 0; kc < 32; kc++) {
                    float4 wn4 = g_C1n[kc * 32 + jc];
                    u64 W[4] = {pk2(wn4.x, wn4.x), pk2(wn4.y, wn4.y),
                                pk2(wn4.z, wn4.z), pk2(wn4.w, wn4.w)};
#pragma unroll
                    for (int c = 0; c < 4; c++)
                        acc = fma2(W[c], h1d[(4 * kc + c) * 8 + rowC], acc);
                }
            } else {
#pragma unroll 2
                for (int kc = 0; kc < 8; kc++) {
                    float4 wn4 = g_C2n[kc * 32 + jc];
                    u64 W[4] = {pk2(wn4.x, wn4.x), pk2(wn4.y, wn4.y),
                                pk2(wn4.z, wn4.z), pk2(wn4.w, wn4.w)};
#pragma unroll
                    for (int c = 0; c < 4; c++)
                        acc = fma2(W[c], h2d[(4 * kc + c) * 8 + rowC], acc);
                }
            }
            cmb[g3 * 1024 + tA] = acc;
        }
        __syncthreads();

        // ======== Phase C elementwise ========
        if (tid < 256) {
            int jcm = tid & 31, row = tid >> 5;
            u64 rz2 = cmb[tid];
            u64 iN2 = cmb[1024 + tid];
            u64 hN2 = cmb[2048 + tid];
            float cr, cz;
            up2(rz2, cr, cz);
            float hold = lo2(h2d[jcm * 8 + row]);
            float rg = sigf(cr), zg = sigf(cz);
            float ng = tanh_(lo2(iN2) + rg * lo2(hN2));
            float v = (1.0f - zg) * ng + zg * hold;
            h2d[jcm * 8 + row] = pk2(v, v);
        }
        __syncthreads();

        // ======== Phase D: projection ========
        if (tid < BT * Vsz) {
            int row = tid / Vsz, j = tid - row * Vsz;
            float acc = b_proj[j];
#pragma unroll
            for (int k = 0; k < 32; k++)
                acc += g_WprojT[k * Vsz + j] * lo2(h2d[k * 8 + row]);
            out[((size_t)(b0 + row) * Ssz + st) * Vsz + j] = acc;
            lg[row * 44 + j] = acc;
        }
        __syncthreads();

        // argmax (overlaps with next step's phase A for other warps)
        if (tid < BT && pred) {
            float best = lg[tid * 44];
            int bi = 0;
#pragma unroll 1
            for (int j = 1; j < Vsz; j++) {
                float v = lg[tid * 44 + j];
                if (v > best) { best = v; bi = j; }
            }
            pred[(size_t)(b0 + tid) * Ssz + st] = (float)bi;
        }
    }
}

// ---------------- launch ----------------
extern "C" void kernel_launch(void* const* d_in, const int* in_sizes, int n_in,
                              void* d_out, int out_size) {
    const float* latent  = (const float*)d_in[0];
    const int*   tokens  = (const int*)d_in[1];
    const float* W_emb   = (const float*)d_in[2];
    const float* b_emb   = (const float*)d_in[3];
    const float* W_init  = (const float*)d_in[4];
    const float* b_init  = (const float*)d_in[5];
    const float* Wih0    = (const float*)d_in[6];
    const float* Whh0    = (const float*)d_in[7];
    const float* bih0    = (const float*)d_in[8];
    const float* bhh0    = (const float*)d_in[9];
    const float* Wih1    = (const float*)d_in[10];
    const float* Whh1    = (const float*)d_in[11];
    const float* bih1    = (const float*)d_in[12];
    const float* bhh1    = (const float*)d_in[13];
    const float* Wih2    = (const float*)d_in[14];
    const float* Whh2    = (const float*)d_in[15];
    const float* bih2    = (const float*)d_in[16];
    const float* bhh2    = (const float*)d_in[17];
    const float* W_proj  = (const float*)d_in[18];
    const float* b_proj  = (const float*)d_in[19];

    float* out = (float*)d_out;
    size_t logits_elems = (size_t)Bsz * Ssz * Vsz;
    float* pred = ((size_t)out_size >= logits_elems + (size_t)Bsz * Ssz)
                      ? out + logits_elems : nullptr;

    cudaFuncSetAttribute(k_main, cudaFuncAttributeMaxDynamicSharedMemorySize, SM_TOTAL);

    k_prep<<<256, 256>>>(latent, W_emb, b_emb, W_init, b_init, Wih0, bih0, Whh0,
                         Wih1, Whh1, Wih2, Whh2, W_proj);
    k_main<<<NCTA, NTHR, SM_TOTAL>>>(tokens, bhh0, bih1, bhh1, bih2, bhh2, b_proj, out, pred);
}

// round 5
// speedup vs baseline: 1.1908x; 1.1908x over previous
#include <cuda_runtime.h>
#include <math.h>

#define Bsz 1024
#define Ssz 350
#define Vsz 41
#define BT 8
#define NCTA 128
#define NTHR 512

typedef unsigned long long u64;

// ---------------- persistent device scratch ----------------
__device__ float4 g_A[49152];      // Whh0 e-pair packed: [kc][gate*256 + c2*128 + j]
__device__ float4 g_B1rz[16384];   // Wih1 (r,z) pairs
__device__ float4 g_B1n[8192];
__device__ float4 g_B2rz[8192];    // Whh1 (r,z)
__device__ float4 g_B2n[4096];
__device__ float4 g_C1rz[2048];    // Wih2
__device__ float4 g_C1n[1024];
__device__ float4 g_C2rz[512];     // Whh2
__device__ float4 g_C2n[256];
__device__ float  g_WprojT[1312];  // [k][j]
__device__ float  g_G0x[41 * 768]; // [v][gate][jm] -> (col jm, col jm+128) pairs
__device__ float  g_Hinit[Bsz * 416];

// ---------------- f32x2 helpers ----------------
__device__ __forceinline__ u64 fma2(u64 a, u64 b, u64 c) {
    u64 d; asm("fma.rn.f32x2 %0,%1,%2,%3;" : "=l"(d) : "l"(a), "l"(b), "l"(c)); return d;
}
__device__ __forceinline__ u64 add2(u64 a, u64 b) {
    u64 d; asm("add.rn.f32x2 %0,%1,%2;" : "=l"(d) : "l"(a), "l"(b)); return d;
}
__device__ __forceinline__ u64 pk2(float x, float y) {
    u64 d; asm("mov.b64 %0,{%1,%2};" : "=l"(d) : "f"(x), "f"(y)); return d;
}
__device__ __forceinline__ void up2(u64 a, float& x, float& y) {
    asm("mov.b64 {%0,%1}, %2;" : "=f"(x), "=f"(y) : "l"(a));
}
__device__ __forceinline__ float lo2(u64 a) { float x, y; up2(a, x, y); return x; }

__device__ __forceinline__ float sigf(float x) {
    return __fdividef(1.0f, 1.0f + __expf(-x));
}
__device__ __forceinline__ float tanh_(float x) {
    float ax = fabsf(x);
    float e = __expf(-2.0f * ax);
    float t = __fdividef(1.0f - e, 1.0f + e);
    return copysignf(t, x);
}

// ---------------- fused prep kernel (unchanged) ----------------
__global__ void k_prep(const float* __restrict__ latent, const float* __restrict__ W_emb,
                       const float* __restrict__ b_emb, const float* __restrict__ W_init,
                       const float* __restrict__ b_init, const float* __restrict__ Wih0,
                       const float* __restrict__ bih0, const float* __restrict__ Whh0,
                       const float* __restrict__ Wih1, const float* __restrict__ Whh1,
                       const float* __restrict__ Wih2, const float* __restrict__ Whh2,
                       const float* __restrict__ W_proj) {
    const int b = blockIdx.x, tid = threadIdx.x;
    const int PTH = 256;
    if (b < 128) {
        __shared__ float lat[8 * 512];
        const int b0 = b * 8;
        for (int i = tid; i < 8 * 512; i += PTH) lat[i] = latent[(size_t)b0 * 512 + i];
        __syncthreads();
        for (int c = tid; c < 416; c += PTH) {
            float acc[8];
            float bi = b_init[c];
#pragma unroll
            for (int r = 0; r < 8; r++) acc[r] = bi;
            const float* w = W_init + (size_t)c * 512;
            for (int k = 0; k < 512; k += 4) {
                float4 wv = *(const float4*)(w + k);
#pragma unroll
                for (int r = 0; r < 8; r++) {
                    acc[r] += wv.x * lat[r * 512 + k];
                    acc[r] += wv.y * lat[r * 512 + k + 1];
                    acc[r] += wv.z * lat[r * 512 + k + 2];
                    acc[r] += wv.w * lat[r * 512 + k + 3];
                }
            }
#pragma unroll
            for (int r = 0; r < 8; r++) g_Hinit[(size_t)(b0 + r) * 416 + c] = acc[r];
        }
    } else if (b < 169) {
        const int v = b - 128;
        __shared__ float emb[512];
        for (int k = tid; k < 512; k += PTH) emb[k] = W_emb[k * Vsz + v] + b_emb[k];
        __syncthreads();
        for (int j = tid; j < 768; j += PTH) {
            float acc = bih0[j];
            const float* w = Wih0 + (size_t)j * 512;
            for (int k = 0; k < 512; k += 4) {
                float4 wv = *(const float4*)(w + k);
                acc += wv.x * emb[k] + wv.y * emb[k + 1] + wv.z * emb[k + 2] + wv.w * emb[k + 3];
            }
            int g = j >> 8, rem = j & 255, e = rem >> 7, jm = rem & 127;
            g_G0x[(((size_t)v * 3 + g) * 128 + jm) * 2 + e] = acc;
        }
    } else {
        const int TOTAL = 90184;
        for (int i = (b - 169) * PTH + tid; i < TOTAL; i += 87 * PTH) {
            if (i < 49152) {
                int kc = i / 768, rem = i % 768;
                int g = rem / 256, rem2 = rem % 256, c2 = rem2 >> 7, jj = rem2 & 127;
                int k = 4 * kc + 2 * c2, row0 = g * 256 + jj, row1 = row0 + 128;
                g_A[i] = make_float4(Whh0[row0 * 256 + k], Whh0[row1 * 256 + k],
                                     Whh0[row0 * 256 + k + 1], Whh0[row1 * 256 + k + 1]);
            } else if (i < 65536) {
                int t = i - 49152;
                int kc = t / 256, c2 = (t & 255) >> 7, jj = t & 127, k = 4 * kc + 2 * c2;
                g_B1rz[t] = make_float4(Wih1[jj * 256 + k], Wih1[(128 + jj) * 256 + k],
                                        Wih1[jj * 256 + k + 1], Wih1[(128 + jj) * 256 + k + 1]);
            } else if (i < 73728) {
                int t = i - 65536;
                int kc = t >> 7, jj = t & 127;
                g_B1n[t] = *(const float4*)&Wih1[(256 + jj) * 256 + 4 * kc];
            } else if (i < 81920) {
                int t = i - 73728;
                int kc = t / 256, c2 = (t & 255) >> 7, jj = t & 127, k = 4 * kc + 2 * c2;
                g_B2rz[t] = make_float4(Whh1[jj * 128 + k], Whh1[(128 + jj) * 128 + k],
                                        Whh1[jj * 128 + k + 1], Whh1[(128 + jj) * 128 + k + 1]);
            } else if (i < 86016) {
                int t = i - 81920;
                int kc = t >> 7, jj = t & 127;
                g_B2n[t] = *(const float4*)&Whh1[(256 + jj) * 128 + 4 * kc];
            } else if (i < 88064) {
                int t = i - 86016;
                int kc = t / 64, c2 = (t & 63) >> 5, jc = t & 31, k = 4 * kc + 2 * c2;
                g_C1rz[t] = make_float4(Wih2[jc * 128 + k], Wih2[(32 + jc) * 128 + k],
                                        Wih2[jc * 128 + k + 1], Wih2[(32 + jc) * 128 + k + 1]);
            } else if (i < 89088) {
                int t = i - 88064;
                int kc = t >> 5, jc = t & 31;
                g_C1n[t] = *(const float4*)&Wih2[(64 + jc) * 128 + 4 * kc];
            } else if (i < 89600) {
                int t = i - 89088;
                int kc = t / 64, c2 = (t & 63) >> 5, jc = t & 31, k = 4 * kc + 2 * c2;
                g_C2rz[t] = make_float4(Whh2[jc * 32 + k], Whh2[(32 + jc) * 32 + k],
                                        Whh2[jc * 32 + k + 1], Whh2[(32 + jc) * 32 + k + 1]);
            } else if (i < 89856) {
                int t = i - 89600;
                int kc = t >> 5, jc = t & 31;
                g_C2n[t] = *(const float4*)&Whh2[(64 + jc) * 32 + 4 * kc];
            } else {
                int t2 = i - 89856;
#pragma unroll
                for (int c = 0; c < 4; c++) {
                    int e = t2 * 4 + c;
                    if (e < 1312) {
                        int k = e / Vsz, j = e - k * Vsz;
                        g_WprojT[e] = W_proj[j * 32 + k];
                    }
                }
            }
        }
    }
}

// ---------------- main persistent GRU kernel (R2 structure, 512 threads, 2 rows/thread) ----------------
__global__ __launch_bounds__(NTHR, 1)
void k_main(const int* __restrict__ tokens,
            const float* __restrict__ bhh0,
            const float* __restrict__ bih1, const float* __restrict__ bhh1,
            const float* __restrict__ bih2, const float* __restrict__ bhh2,
            const float* __restrict__ b_proj,
            float* __restrict__ out, float* __restrict__ pred) {
    __shared__ __align__(16) u64 h0d[256 * 8];
    __shared__ __align__(16) u64 h1d[128 * 8];
    __shared__ __align__(16) u64 h2d[32 * 8];
    __shared__ int toksAll[Ssz * 8];
    __shared__ float lg[BT][44];

    const int tid = threadIdx.x;
    const int b0 = blockIdx.x * BT;
    const int jj = tid & 127;
    const int r0 = (tid >> 7) * 2;   // 2 rows per thread
    const int jc = tid & 31;
    const int rowC = (tid >> 5) & 7;

    // tokens preload (SOS at step 0)
    for (int i = tid; i < Ssz * 8; i += NTHR) {
        int stt = i >> 3, row = i & 7;
        toksAll[i] = (stt == 0) ? 1 : tokens[(size_t)(b0 + row) * Ssz + stt];
    }

    // initial state -> dup smem
    for (int idx = tid; idx < BT * 416; idx += NTHR) {
        int row = idx / 416, c = idx - row * 416;
        float v = g_Hinit[(size_t)(b0 + row) * 416 + c];
        if (c < 256)      h0d[c * 8 + row] = pk2(v, v);
        else if (c < 384) h1d[(c - 256) * 8 + row] = pk2(v, v);
        else              h2d[(c - 384) * 8 + row] = pk2(v, v);
    }

    // register-resident packed biases (same as R2)
    const u64 bA_r = pk2(bhh0[jj], bhh0[128 + jj]);
    const u64 bA_z = pk2(bhh0[256 + jj], bhh0[384 + jj]);
    const u64 bA_n = pk2(bhh0[512 + jj], bhh0[640 + jj]);
    const u64 bB_rz = pk2(bih1[jj] + bhh1[jj], bih1[128 + jj] + bhh1[128 + jj]);
    const float b1in = bih1[256 + jj], b1hn = bhh1[256 + jj];
    const u64 bB_in = pk2(b1in, b1in);
    const u64 bB_hn = pk2(b1hn, b1hn);
    const u64 bC_rz = pk2(bih2[jc] + bhh2[jc], bih2[32 + jc] + bhh2[32 + jc]);
    const float b2in = bih2[64 + jc], b2hn = bhh2[64 + jc];
    const u64 bC_in = pk2(b2in, b2in);
    const u64 bC_hn = pk2(b2hn, b2hn);

    const u64* __restrict__ G0p = (const u64*)g_G0x;

    __syncthreads();

    for (int st = 0; st < Ssz; st++) {
        const int* tokrow = toksAll + st * 8;

        // ======== Phase A: layer 0 (e-pair packed), rows r0..r0+1 ========
        u64 aR[2], aZ[2], aN[2], gIN[2];
#pragma unroll
        for (int r = 0; r < 2; r++) {
            const u64* g = G0p + (size_t)tokrow[r0 + r] * 384;
            aR[r] = add2(g[jj], bA_r);
            aZ[r] = add2(g[128 + jj], bA_z);
            gIN[r] = g[256 + jj];
            aN[r] = bA_n;
        }
        for (int kc = 0; kc < 64; kc++) {
            const float4* base = g_A + kc * 768;
            ulonglong2 wr0 = *(const ulonglong2*)(base + jj);
            ulonglong2 wr1 = *(const ulonglong2*)(base + 128 + jj);
            ulonglong2 wz0 = *(const ulonglong2*)(base + 256 + jj);
            ulonglong2 wz1 = *(const ulonglong2*)(base + 384 + jj);
            ulonglong2 wn0 = *(const ulonglong2*)(base + 512 + jj);
            ulonglong2 wn1 = *(const ulonglong2*)(base + 640 + jj);
            u64 wR[4] = {wr0.x, wr0.y, wr1.x, wr1.y};
            u64 wZ[4] = {wz0.x, wz0.y, wz1.x, wz1.y};
            u64 wN[4] = {wn0.x, wn0.y, wn1.x, wn1.y};
            u64 hv[4][2];
#pragma unroll
            for (int c = 0; c < 4; c++) {
                ulonglong2 ha = *(const ulonglong2*)&h0d[(4 * kc + c) * 8 + r0];
                hv[c][0] = ha.x; hv[c][1] = ha.y;
            }
#pragma unroll
            for (int c = 0; c < 4; c++)
#pragma unroll
                for (int r = 0; r < 2; r++) {
                    aR[r] = fma2(wR[c], hv[c][r], aR[r]);
                    aZ[r] = fma2(wZ[c], hv[c][r], aZ[r]);
                    aN[r] = fma2(wN[c], hv[c][r], aN[r]);
                }
        }
        __syncthreads();
#pragma unroll
        for (int r = 0; r < 2; r++) {
            float r0e, r1e, z0e, z1e, n0e, n1e, i0e, i1e;
            up2(aR[r], r0e, r1e); up2(aZ[r], z0e, z1e);
            up2(aN[r], n0e, n1e); up2(gIN[r], i0e, i1e);
            float hold0 = lo2(h0d[jj * 8 + r0 + r]);
            float hold1 = lo2(h0d[(128 + jj) * 8 + r0 + r]);
            float rg0 = sigf(r0e), rg1 = sigf(r1e);
            float zg0 = sigf(z0e), zg1 = sigf(z1e);
            float ng0 = tanh_(i0e + rg0 * n0e), ng1 = tanh_(i1e + rg1 * n1e);
            float v0 = (1.0f - zg0) * ng0 + zg0 * hold0;
            float v1 = (1.0f - zg1) * ng1 + zg1 * hold1;
            h0d[jj * 8 + r0 + r] = pk2(v0, v0);
            h0d[(128 + jj) * 8 + r0 + r] = pk2(v1, v1);
        }
        __syncthreads();

        // ======== Phase B: layer 1 (gate-pair packed) ========
        u64 rz[2], iN[2], hN[2];
#pragma unroll
        for (int r = 0; r < 2; r++) { rz[r] = bB_rz; iN[r] = bB_in; hN[r] = bB_hn; }
        for (int kc = 0; kc < 64; kc++) {
            const float4* brz = g_B1rz + kc * 256;
            ulonglong2 w01 = *(const ulonglong2*)(brz + jj);
            ulonglong2 w23 = *(const ulonglong2*)(brz + 128 + jj);
            float4 wn4 = g_B1n[kc * 128 + jj];
            u64 wrz[4] = {w01.x, w01.y, w23.x, w23.y};
            u64 wnd[4] = {pk2(wn4.x, wn4.x), pk2(wn4.y, wn4.y),
                          pk2(wn4.z, wn4.z), pk2(wn4.w, wn4.w)};
            u64 hv[4][2];
#pragma unroll
            for (int c = 0; c < 4; c++) {
                ulonglong2 ha = *(const ulonglong2*)&h0d[(4 * kc + c) * 8 + r0];
                hv[c][0] = ha.x; hv[c][1] = ha.y;
            }
#pragma unroll
            for (int c = 0; c < 4; c++)
#pragma unroll
                for (int r = 0; r < 2; r++) {
                    rz[r] = fma2(wrz[c], hv[c][r], rz[r]);
                    iN[r] = fma2(wnd[c], hv[c][r], iN[r]);
                }
        }
        for (int kc = 0; kc < 32; kc++) {
            const float4* brz = g_B2rz + kc * 256;
            ulonglong2 w01 = *(const ulonglong2*)(brz + jj);
            ulonglong2 w23 = *(const ulonglong2*)(brz + 128 + jj);
            float4 wn4 = g_B2n[kc * 128 + jj];
            u64 wrz[4] = {w01.x, w01.y, w23.x, w23.y};
            u64 wnd[4] = {pk2(wn4.x, wn4.x), pk2(wn4.y, wn4.y),
                          pk2(wn4.z, wn4.z), pk2(wn4.w, wn4.w)};
            u64 hv[4][2];
#pragma unroll
            for (int c = 0; c < 4; c++) {
                ulonglong2 ha = *(const ulonglong2*)&h1d[(4 * kc + c) * 8 + r0];
                hv[c][0] = ha.x; hv[c][1] = ha.y;
            }
#pragma unroll
            for (int c = 0; c < 4; c++)
#pragma unroll
                for (int r = 0; r < 2; r++) {
                    rz[r] = fma2(wrz[c], hv[c][r], rz[r]);
                    hN[r] = fma2(wnd[c], hv[c][r], hN[r]);
                }
        }
        __syncthreads();
#pragma unroll
        for (int r = 0; r < 2; r++) {
            float ar, az;
            up2(rz[r], ar, az);
            float hold = lo2(h1d[jj * 8 + r0 + r]);
            float rg = sigf(ar), zg = sigf(az);
            float ng = tanh_(lo2(iN[r]) + rg * lo2(hN[r]));
            float v = (1.0f - zg) * ng + zg * hold;
            h1d[jj * 8 + r0 + r] = pk2(v, v);
        }
        __syncthreads();

        // ======== Phase C: layer 2 (first 256 threads, as R2) ========
        if (tid < 256) {
            u64 rz2 = bC_rz, iN2 = bC_in, hN2 = bC_hn;
            for (int kc = 0; kc < 32; kc++) {
                const float4* brz = g_C1rz + kc * 64;
                ulonglong2 w01 = *(const ulonglong2*)(brz + jc);
                ulonglong2 w23 = *(const ulonglong2*)(brz + 32 + jc);
                float4 wn4 = g_C1n[kc * 32 + jc];
                u64 wrz[4] = {w01.x, w01.y, w23.x, w23.y};
                u64 wnd[4] = {pk2(wn4.x, wn4.x), pk2(wn4.y, wn4.y),
                              pk2(wn4.z, wn4.z), pk2(wn4.w, wn4.w)};
#pragma unroll
                for (int c = 0; c < 4; c++) {
                    u64 h = h1d[(4 * kc + c) * 8 + rowC];
                    rz2 = fma2(wrz[c], h, rz2);
                    iN2 = fma2(wnd[c], h, iN2);
                }
            }
            for (int kc = 0; kc < 8; kc++) {
                const float4* brz = g_C2rz + kc * 64;
                ulonglong2 w01 = *(const ulonglong2*)(brz + jc);
                ulonglong2 w23 = *(const ulonglong2*)(brz + 32 + jc);
                float4 wn4 = g_C2n[kc * 32 + jc];
                u64 wrz[4] = {w01.x, w01.y, w23.x, w23.y};
                u64 wnd[4] = {pk2(wn4.x, wn4.x), pk2(wn4.y, wn4.y),
                              pk2(wn4.z, wn4.z), pk2(wn4.w, wn4.w)};
#pragma unroll
                for (int c = 0; c < 4; c++) {
                    u64 h = h2d[(4 * kc + c) * 8 + rowC];
                    rz2 = fma2(wrz[c], h, rz2);
                    hN2 = fma2(wnd[c], h, hN2);
                }
            }
            __syncthreads();
            {
                float cr, cz;
                up2(rz2, cr, cz);
                float hold = lo2(h2d[jc * 8 + rowC]);
                float rg = sigf(cr), zg = sigf(cz);
                float ng = tanh_(lo2(iN2) + rg * lo2(hN2));
                float v = (1.0f - zg) * ng + zg * hold;
                h2d[jc * 8 + rowC] = pk2(v, v);
            }
        } else {
            __syncthreads();
        }
        __syncthreads();

        // ======== Phase D: projection + argmax ========
        if (tid < BT * Vsz) {
            int row = tid / Vsz, j = tid - row * Vsz;
            float acc = b_proj[j];
#pragma unroll
            for (int k = 0; k < 32; k++)
                acc += g_WprojT[k * Vsz + j] * lo2(h2d[k * 8 + row]);
            out[((size_t)(b0 + row) * Ssz + st) * Vsz + j] = acc;
            lg[row][j] = acc;
        }
        __syncthreads();
        if (tid < BT && pred) {
            float best = lg[tid][0];
            int bi = 0;
#pragma unroll 1
            for (int j = 1; j < Vsz; j++) {
                float v = lg[tid][j];
                if (v > best) { best = v; bi = j; }
            }
            pred[(size_t)(b0 + tid) * Ssz + st] = (float)bi;
        }
        __syncthreads();
    }
}

// ---------------- launch ----------------
extern "C" void kernel_launch(void* const* d_in, const int* in_sizes, int n_in,
                              void* d_out, int out_size) {
    const float* latent  = (const float*)d_in[0];
    const int*   tokens  = (const int*)d_in[1];
    const float* W_emb   = (const float*)d_in[2];
    const float* b_emb   = (const float*)d_in[3];
    const float* W_init  = (const float*)d_in[4];
    const float* b_init  = (const float*)d_in[5];
    const float* Wih0    = (const float*)d_in[6];
    const float* Whh0    = (const float*)d_in[7];
    const float* bih0    = (const float*)d_in[8];
    const float* bhh0    = (const float*)d_in[9];
    const float* Wih1    = (const float*)d_in[10];
    const float* Whh1    = (const float*)d_in[11];
    const float* bih1    = (const float*)d_in[12];
    const float* bhh1    = (const float*)d_in[13];
    const float* Wih2    = (const float*)d_in[14];
    const float* Whh2    = (const float*)d_in[15];
    const float* bih2    = (const float*)d_in[16];
    const float* bhh2    = (const float*)d_in[17];
    const float* W_proj  = (const float*)d_in[18];
    const float* b_proj  = (const float*)d_in[19];

    float* out = (float*)d_out;
    size_t logits_elems = (size_t)Bsz * Ssz * Vsz;
    float* pred = ((size_t)out_size >= logits_elems + (size_t)Bsz * Ssz)
                      ? out + logits_elems : nullptr;

    k_prep<<<256, 256>>>(latent, W_emb, b_emb, W_init, b_init, Wih0, bih0, Whh0,
                         Wih1, Whh1, Wih2, Whh2, W_proj);
    k_main<<<NCTA, NTHR>>>(tokens, bhh0, bih1, bhh1, bih2, bhh2, b_proj, out, pred);
}

// round 7
// speedup vs baseline: 1.2237x; 1.0277x over previous
#include <cuda_runtime.h>
#include <math.h>

#define Bsz 1024
#define Ssz 350
#define Vsz 41
#define BT 8
#define NCTA 128
#define NTHR 512

typedef unsigned long long u64;

// ---------------- persistent device scratch ----------------
__device__ float4 g_A[49152];      // Whh0 pair packed: [kc][gate*256 + c2*128 + jj]
__device__ float4 g_B1rz[16384];   // Wih1 (r,z) pairs
__device__ float4 g_B1n[8192];     // Wih1 n rows
__device__ float4 g_B2rz[8192];    // Whh1 (r,z)
__device__ float4 g_B2n[4096];     // Whh1 n
__device__ float4 g_C1rz[2048];    // Wih2
__device__ float4 g_C1n[1024];
__device__ float4 g_C2rz[512];     // Whh2
__device__ float4 g_C2n[256];
__device__ float  g_WprojT[1312];  // [k][j]
__device__ float  g_G0x[41 * 768]; // [v][gate][jm] -> (col jm, col jm+128) pairs
__device__ float  g_Hinit[Bsz * 416];

// ---------------- f32x2 helpers ----------------
__device__ __forceinline__ u64 fma2(u64 a, u64 b, u64 c) {
    u64 d; asm("fma.rn.f32x2 %0,%1,%2,%3;" : "=l"(d) : "l"(a), "l"(b), "l"(c)); return d;
}
__device__ __forceinline__ u64 add2(u64 a, u64 b) {
    u64 d; asm("add.rn.f32x2 %0,%1,%2;" : "=l"(d) : "l"(a), "l"(b)); return d;
}
__device__ __forceinline__ u64 pk2(float x, float y) {
    u64 d; asm("mov.b64 %0,{%1,%2};" : "=l"(d) : "f"(x), "f"(y)); return d;
}
__device__ __forceinline__ void up2(u64 a, float& x, float& y) {
    asm("mov.b64 {%0,%1}, %2;" : "=f"(x), "=f"(y) : "l"(a));
}
__device__ __forceinline__ float lo2(u64 a) { float x, y; up2(a, x, y); return x; }

__device__ __forceinline__ float sigf(float x) {
    return __fdividef(1.0f, 1.0f + __expf(-x));
}
__device__ __forceinline__ float tanh_(float x) {
    float ax = fabsf(x);
    float e = __expf(-2.0f * ax);
    float t = __fdividef(1.0f - e, 1.0f + e);
    return copysignf(t, x);
}

// ---------------- fused prep kernel (identical to R2/R5) ----------------
__global__ void k_prep(const float* __restrict__ latent, const float* __restrict__ W_emb,
                       const float* __restrict__ b_emb, const float* __restrict__ W_init,
                       const float* __restrict__ b_init, const float* __restrict__ Wih0,
                       const float* __restrict__ bih0, const float* __restrict__ Whh0,
                       const float* __restrict__ Wih1, const float* __restrict__ Whh1,
                       const float* __restrict__ Wih2, const float* __restrict__ Whh2,
                       const float* __restrict__ W_proj) {
    const int b = blockIdx.x, tid = threadIdx.x;
    const int PTH = 256;
    if (b < 128) {
        __shared__ float lat[8 * 512];
        const int b0 = b * 8;
        for (int i = tid; i < 8 * 512; i += PTH) lat[i] = latent[(size_t)b0 * 512 + i];
        __syncthreads();
        for (int c = tid; c < 416; c += PTH) {
            float acc[8];
            float bi = b_init[c];
#pragma unroll
            for (int r = 0; r < 8; r++) acc[r] = bi;
            const float* w = W_init + (size_t)c * 512;
            for (int k = 0; k < 512; k += 4) {
                float4 wv = *(const float4*)(w + k);
#pragma unroll
                for (int r = 0; r < 8; r++) {
                    acc[r] += wv.x * lat[r * 512 + k];
                    acc[r] += wv.y * lat[r * 512 + k + 1];
                    acc[r] += wv.z * lat[r * 512 + k + 2];
                    acc[r] += wv.w * lat[r * 512 + k + 3];
                }
            }
#pragma unroll
            for (int r = 0; r < 8; r++) g_Hinit[(size_t)(b0 + r) * 416 + c] = acc[r];
        }
    } else if (b < 169) {
        const int v = b - 128;
        __shared__ float emb[512];
        for (int k = tid; k < 512; k += PTH) emb[k] = W_emb[k * Vsz + v] + b_emb[k];
        __syncthreads();
        for (int j = tid; j < 768; j += PTH) {
            float acc = bih0[j];
            const float* w = Wih0 + (size_t)j * 512;
            for (int k = 0; k < 512; k += 4) {
                float4 wv = *(const float4*)(w + k);
                acc += wv.x * emb[k] + wv.y * emb[k + 1] + wv.z * emb[k + 2] + wv.w * emb[k + 3];
            }
            int g = j >> 8, rem = j & 255, e = rem >> 7, jm = rem & 127;
            g_G0x[(((size_t)v * 3 + g) * 128 + jm) * 2 + e] = acc;
        }
    } else {
        const int TOTAL = 90184;
        for (int i = (b - 169) * PTH + tid; i < TOTAL; i += 87 * PTH) {
            if (i < 49152) {
                int kc = i / 768, rem = i % 768;
                int g = rem / 256, rem2 = rem % 256, c2 = rem2 >> 7, jj = rem2 & 127;
                int k = 4 * kc + 2 * c2, row0 = g * 256 + jj, row1 = row0 + 128;
                g_A[i] = make_float4(Whh0[row0 * 256 + k], Whh0[row1 * 256 + k],
                                     Whh0[row0 * 256 + k + 1], Whh0[row1 * 256 + k + 1]);
            } else if (i < 65536) {
                int t = i - 49152;
                int kc = t / 256, c2 = (t & 255) >> 7, jj = t & 127, k = 4 * kc + 2 * c2;
                g_B1rz[t] = make_float4(Wih1[jj * 256 + k], Wih1[(128 + jj) * 256 + k],
                                        Wih1[jj * 256 + k + 1], Wih1[(128 + jj) * 256 + k + 1]);
            } else if (i < 73728) {
                int t = i - 65536;
                int kc = t >> 7, jj = t & 127;
                g_B1n[t] = *(const float4*)&Wih1[(256 + jj) * 256 + 4 * kc];
            } else if (i < 81920) {
                int t = i - 73728;
                int kc = t / 256, c2 = (t & 255) >> 7, jj = t & 127, k = 4 * kc + 2 * c2;
                g_B2rz[t] = make_float4(Whh1[jj * 128 + k], Whh1[(128 + jj) * 128 + k],
                                        Whh1[jj * 128 + k + 1], Whh1[(128 + jj) * 128 + k + 1]);
            } else if (i < 86016) {
                int t = i - 81920;
                int kc = t >> 7, jj = t & 127;
                g_B2n[t] = *(const float4*)&Whh1[(256 + jj) * 128 + 4 * kc];
            } else if (i < 88064) {
                int t = i - 86016;
                int kc = t / 64, c2 = (t & 63) >> 5, jc = t & 31, k = 4 * kc + 2 * c2;
                g_C1rz[t] = make_float4(Wih2[jc * 128 + k], Wih2[(32 + jc) * 128 + k],
                                        Wih2[jc * 128 + k + 1], Wih2[(32 + jc) * 128 + k + 1]);
            } else if (i < 89088) {
                int t = i - 88064;
                int kc = t >> 5, jc = t & 31;
                g_C1n[t] = *(const float4*)&Wih2[(64 + jc) * 128 + 4 * kc];
            } else if (i < 89600) {
                int t = i - 89088;
                int kc = t / 64, c2 = (t & 63) >> 5, jc = t & 31, k = 4 * kc + 2 * c2;
                g_C2rz[t] = make_float4(Whh2[jc * 32 + k], Whh2[(32 + jc) * 32 + k],
                                        Whh2[jc * 32 + k + 1], Whh2[(32 + jc) * 32 + k + 1]);
            } else if (i < 89856) {
                int t = i - 89600;
                int kc = t >> 5, jc = t & 31;
                g_C2n[t] = *(const float4*)&Whh2[(64 + jc) * 32 + 4 * kc];
            } else {
                int t2 = i - 89856;
#pragma unroll
                for (int c = 0; c < 4; c++) {
                    int e = t2 * 4 + c;
                    if (e < 1312) {
                        int k = e / Vsz, j = e - k * Vsz;
                        g_WprojT[e] = W_proj[j * 32 + k];
                    }
                }
            }
        }
    }
}

// ---------------- dynamic smem layout (bytes) ----------------
#define OFF_H0   0        // u64[256*8]  dup pairs (col-major, 8 rows)
#define OFF_H1   16384    // u64[128*8]
#define OFF_H2   24576    // u64[32*8]
#define OFF_CMB  26624    // u64[3072]   window scratch
#define OFF_BHN  51200    // u64[1024]   B hN partials
#define OFF_CHN  59392    // u64[256]    C hN partials
#define OFF_TOK  61440    // int[350*8]
#define OFF_LG   72640    // float[8*44]
#define SM_TOTAL 74048

// ---------------- main persistent GRU kernel ----------------
__global__ __launch_bounds__(NTHR, 1)
void k_main(const int* __restrict__ tokens,
            const float* __restrict__ bhh0,
            const float* __restrict__ bih1, const float* __restrict__ bhh1,
            const float* __restrict__ bih2, const float* __restrict__ bhh2,
            const float* __restrict__ b_proj,
            float* __restrict__ out, float* __restrict__ pred) {
    extern __shared__ __align__(16) char smraw[];
    u64* h0d = (u64*)(smraw + OFF_H0);
    u64* h1d = (u64*)(smraw + OFF_H1);
    u64* h2d = (u64*)(smraw + OFF_H2);
    u64* cmb = (u64*)(smraw + OFF_CMB);
    u64* cBHN = (u64*)(smraw + OFF_BHN);
    u64* cCHN = (u64*)(smraw + OFF_CHN);
    int* toksAll = (int*)(smraw + OFF_TOK);
    float* lg = (float*)(smraw + OFF_LG);

    const int tid = threadIdx.x;
    const int b0 = blockIdx.x * BT;

    // tokens preload (SOS at step 0)
    for (int i = tid; i < Ssz * 8; i += NTHR) {
        int stt = i >> 3, row = i & 7;
        toksAll[i] = (stt == 0) ? 1 : tokens[(size_t)(b0 + row) * Ssz + stt];
    }
    // initial state -> dup smem
    for (int idx = tid; idx < BT * 416; idx += NTHR) {
        int row = idx / 416, c = idx - row * 416;
        float v = g_Hinit[(size_t)(b0 + row) * 416 + c];
        if (c < 256)      h0d[c * 8 + row] = pk2(v, v);
        else if (c < 384) h1d[(c - 256) * 8 + row] = pk2(v, v);
        else              h2d[(c - 384) * 8 + row] = pk2(v, v);
    }

    // ---- per-thread roles & biases ----
    const int gA = tid >> 7;                 // window1 group 0..3
    const int jjA = tid & 127;
    const u64 bA = (gA < 3) ? pk2(bhh0[gA * 256 + jjA], bhh0[gA * 256 + 128 + jjA]) : 0ull;
    const u64 bBhn = pk2(bhh1[256 + jjA], bhh1[256 + jjA]);   // used by gA==3
    const int jcH = tid & 31, rqH = (tid >> 5) & 3;           // gA==3 C-hN role
    const u64 bChn = pk2(bhh2[64 + jcH], bhh2[64 + jcH]);
    // window2: role 0/1 rz rows, role 2/3 iN rows
    const int roleB = tid >> 7;
    const int jjB = tid & 127;
    const int r0B = (roleB & 1) * 4;
    const u64 bBrz = pk2(bih1[jjB] + bhh1[jjB], bih1[128 + jjB] + bhh1[128 + jjB]);
    const u64 bBin = pk2(bih1[256 + jjB], bih1[256 + jjB]);
    // C window: tid<64 rz, 64..127 iN
    const int jcC = tid & 31;
    const int r0C = ((tid >> 5) & 1) * 4;
    const u64 bCrz = pk2(bih2[jcC] + bhh2[jcC], bih2[32 + jcC] + bhh2[32 + jcC]);
    const u64 bCin = pk2(bih2[64 + jcC], bih2[64 + jcC]);
    // D role
    const int rowD = tid / Vsz;
    const int jD = tid - rowD * Vsz;
    const float bpjD = (tid < BT * Vsz) ? b_proj[jD] : 0.f;

    const u64* __restrict__ G0p = (const u64*)g_G0x;

    __syncthreads();

    for (int st = 0; st < Ssz; st++) {
        const int* tokrow = toksAll + st * 8;

        // ======== Window 1: layer-0 gates (g0..g2) + B-hN/C-hN (g3) ========
        if (gA < 3) {
            u64 acc[8];
            if (gA < 2) {
#pragma unroll
                for (int r = 0; r < 8; r++)
                    acc[r] = add2(G0p[(size_t)tokrow[r] * 384 + gA * 128 + jjA], bA);
            } else {
#pragma unroll
                for (int r = 0; r < 8; r++) acc[r] = bA;
            }
            const float4* gb = g_A + gA * 256 + jjA;
            ulonglong2 cw0 = *(const ulonglong2*)gb;
            ulonglong2 cw1 = *(const ulonglong2*)(gb + 128);
            for (int kc = 0; kc < 64; kc++) {
                int nkc = (kc + 1) & 63;
                ulonglong2 nw0 = *(const ulonglong2*)(gb + nkc * 768);
                ulonglong2 nw1 = *(const ulonglong2*)(gb + nkc * 768 + 128);
                u64 W[4] = {cw0.x, cw0.y, cw1.x, cw1.y};
#pragma unroll
                for (int c = 0; c < 4; c++) {
                    const u64* hA = h0d + (4 * kc + c) * 8;
                    ulonglong2 h01 = *(const ulonglong2*)(hA + 0);
                    ulonglong2 h23 = *(const ulonglong2*)(hA + 2);
                    ulonglong2 h45 = *(const ulonglong2*)(hA + 4);
                    ulonglong2 h67 = *(const ulonglong2*)(hA + 6);
                    acc[0] = fma2(W[c], h01.x, acc[0]);
                    acc[1] = fma2(W[c], h01.y, acc[1]);
                    acc[2] = fma2(W[c], h23.x, acc[2]);
                    acc[3] = fma2(W[c], h23.y, acc[3]);
                    acc[4] = fma2(W[c], h45.x, acc[4]);
                    acc[5] = fma2(W[c], h45.y, acc[5]);
                    acc[6] = fma2(W[c], h67.x, acc[6]);
                    acc[7] = fma2(W[c], h67.y, acc[7]);
                }
                cw0 = nw0; cw1 = nw1;
            }
#pragma unroll
            for (int r = 0; r < 8; r++) cmb[(gA * 8 + r) * 128 + jjA] = acc[r];
        } else {
            // B-hN: Whh1 n-gate over OLD h1, 8 rows
            u64 acc[8];
#pragma unroll
            for (int r = 0; r < 8; r++) acc[r] = bBhn;
            for (int kc = 0; kc < 32; kc++) {
                float4 wn4 = g_B2n[kc * 128 + jjA];
                u64 W[4] = {pk2(wn4.x, wn4.x), pk2(wn4.y, wn4.y),
                            pk2(wn4.z, wn4.z), pk2(wn4.w, wn4.w)};
#pragma unroll
                for (int c = 0; c < 4; c++) {
                    const u64* hA = h1d + (4 * kc + c) * 8;
                    ulonglong2 h01 = *(const ulonglong2*)(hA + 0);
                    ulonglong2 h23 = *(const ulonglong2*)(hA + 2);
                    ulonglong2 h45 = *(const ulonglong2*)(hA + 4);
                    ulonglong2 h67 = *(const ulonglong2*)(hA + 6);
                    acc[0] = fma2(W[c], h01.x, acc[0]);
                    acc[1] = fma2(W[c], h01.y, acc[1]);
                    acc[2] = fma2(W[c], h23.x, acc[2]);
                    acc[3] = fma2(W[c], h23.y, acc[3]);
                    acc[4] = fma2(W[c], h45.x, acc[4]);
                    acc[5] = fma2(W[c], h45.y, acc[5]);
                    acc[6] = fma2(W[c], h67.x, acc[6]);
                    acc[7] = fma2(W[c], h67.y, acc[7]);
                }
            }
#pragma unroll
            for (int r = 0; r < 8; r++) cBHN[r * 128 + jjA] = acc[r];
            // C-hN: Whh2 n-gate over OLD h2, rows 2*rqH, 2*rqH+1
            u64 a0 = bChn, a1 = bChn;
            for (int kc = 0; kc < 8; kc++) {
                float4 wn4 = g_C2n[kc * 32 + jcH];
                u64 W[4] = {pk2(wn4.x, wn4.x), pk2(wn4.y, wn4.y),
                            pk2(wn4.z, wn4.z), pk2(wn4.w, wn4.w)};
#pragma unroll
                for (int c = 0; c < 4; c++) {
                    const u64* hA = h2d + (4 * kc + c) * 8 + 2 * rqH;
                    a0 = fma2(W[c], hA[0], a0);
                    a1 = fma2(W[c], hA[1], a1);
                }
            }
            cCHN[(2 * rqH) * 32 + jcH] = a0;
            cCHN[(2 * rqH + 1) * 32 + jcH] = a1;
        }
        __syncthreads();

        // ======== A combine: 1024 pair-rows over 512 threads ========
        for (int q = tid; q < 1024; q += NTHR) {
            int jm = q & 127, row = q >> 7;
            u64 aR = cmb[(0 + row) * 128 + jm];
            u64 aZ = cmb[(8 + row) * 128 + jm];
            u64 aN = cmb[(16 + row) * 128 + jm];
            u64 gIN = G0p[(size_t)tokrow[row] * 384 + 256 + jm];
            float r0e, r1e, z0e, z1e, n0e, n1e, i0e, i1e;
            up2(aR, r0e, r1e); up2(aZ, z0e, z1e);
            up2(aN, n0e, n1e); up2(gIN, i0e, i1e);
            float hold0 = lo2(h0d[jm * 8 + row]);
            float hold1 = lo2(h0d[(128 + jm) * 8 + row]);
            float rg0 = sigf(r0e), rg1 = sigf(r1e);
            float zg0 = sigf(z0e), zg1 = sigf(z1e);
            float ng0 = tanh_(i0e + rg0 * n0e), ng1 = tanh_(i1e + rg1 * n1e);
            float v0 = (1.0f - zg0) * ng0 + zg0 * hold0;
            float v1 = (1.0f - zg1) * ng1 + zg1 * hold1;
            h0d[jm * 8 + row] = pk2(v0, v0);
            h0d[(128 + jm) * 8 + row] = pk2(v1, v1);
        }
        __syncthreads();

        // ======== Window 2: layer-1 rz (roles 0/1) + iN (roles 2/3) ========
        if (roleB < 2) {
            u64 acc[4];
#pragma unroll
            for (int i = 0; i < 4; i++) acc[i] = bBrz;
            const float4* gb1 = g_B1rz + jjB;
            ulonglong2 cw0 = *(const ulonglong2*)gb1;
            ulonglong2 cw1 = *(const ulonglong2*)(gb1 + 128);
            for (int kc = 0; kc < 64; kc++) {
                int nkc = (kc + 1) & 63;
                ulonglong2 nw0 = *(const ulonglong2*)(gb1 + nkc * 256);
                ulonglong2 nw1 = *(const ulonglong2*)(gb1 + nkc * 256 + 128);
                u64 W[4] = {cw0.x, cw0.y, cw1.x, cw1.y};
#pragma unroll
                for (int c = 0; c < 4; c++) {
                    const u64* hA = h0d + (4 * kc + c) * 8 + r0B;
                    ulonglong2 hx = *(const ulonglong2*)(hA + 0);
                    ulonglong2 hy = *(const ulonglong2*)(hA + 2);
                    acc[0] = fma2(W[c], hx.x, acc[0]);
                    acc[1] = fma2(W[c], hx.y, acc[1]);
                    acc[2] = fma2(W[c], hy.x, acc[2]);
                    acc[3] = fma2(W[c], hy.y, acc[3]);
                }
                cw0 = nw0; cw1 = nw1;
            }
            const float4* gb2 = g_B2rz + jjB;
            ulonglong2 dw0 = *(const ulonglong2*)gb2;
            ulonglong2 dw1 = *(const ulonglong2*)(gb2 + 128);
            for (int kc = 0; kc < 32; kc++) {
                int nkc = (kc + 1) & 31;
                ulonglong2 nw0 = *(const ulonglong2*)(gb2 + nkc * 256);
                ulonglong2 nw1 = *(const ulonglong2*)(gb2 + nkc * 256 + 128);
                u64 W[4] = {dw0.x, dw0.y, dw1.x, dw1.y};
#pragma unroll
                for (int c = 0; c < 4; c++) {
                    const u64* hA = h1d + (4 * kc + c) * 8 + r0B;
                    ulonglong2 hx = *(const ulonglong2*)(hA + 0);
                    ulonglong2 hy = *(const ulonglong2*)(hA + 2);
                    acc[0] = fma2(W[c], hx.x, acc[0]);
                    acc[1] = fma2(W[c], hx.y, acc[1]);
                    acc[2] = fma2(W[c], hy.x, acc[2]);
                    acc[3] = fma2(W[c], hy.y, acc[3]);
                }
                dw0 = nw0; dw1 = nw1;
            }
#pragma unroll
            for (int i = 0; i < 4; i++) cmb[(r0B + i) * 128 + jjB] = acc[i];
        } else {
            u64 acc[4];
#pragma unroll
            for (int i = 0; i < 4; i++) acc[i] = bBin;
            for (int kc = 0; kc < 64; kc++) {
                float4 wn4 = g_B1n[kc * 128 + jjB];
                u64 W[4] = {pk2(wn4.x, wn4.x), pk2(wn4.y, wn4.y),
                            pk2(wn4.z, wn4.z), pk2(wn4.w, wn4.w)};
#pragma unroll
                for (int c = 0; c < 4; c++) {
                    const u64* hA = h0d + (4 * kc + c) * 8 + r0B;
                    ulonglong2 hx = *(const ulonglong2*)(hA + 0);
                    ulonglong2 hy = *(const ulonglong2*)(hA + 2);
                    acc[0] = fma2(W[c], hx.x, acc[0]);
                    acc[1] = fma2(W[c], hx.y, acc[1]);
                    acc[2] = fma2(W[c], hy.x, acc[2]);
                    acc[3] = fma2(W[c], hy.y, acc[3]);
                }
            }
#pragma unroll
            for (int i = 0; i < 4; i++) cmb[1024 + (r0B + i) * 128 + jjB] = acc[i];
        }
        __syncthreads();

        // ======== B combine: 1024 items ========
        for (int q = tid; q < 1024; q += NTHR) {
            int jm = q & 127, row = q >> 7;
            u64 rzv = cmb[row * 128 + jm];
            u64 iN = cmb[1024 + row * 128 + jm];
            u64 hN = cBHN[row * 128 + jm];
            float ar, az;
            up2(rzv, ar, az);
            float hold = lo2(h1d[jm * 8 + row]);
            float rg = sigf(ar), zg = sigf(az);
            float ng = tanh_(lo2(iN) + rg * lo2(hN));
            float v = (1.0f - zg) * ng + zg * hold;
            h1d[jm * 8 + row] = pk2(v, v);
        }
        __syncthreads();

        // ======== Window 3: layer-2 rz (tid<64) + iN (tid 64..127) ========
        if (tid < 64) {
            u64 acc[4];
#pragma unroll
            for (int i = 0; i < 4; i++) acc[i] = bCrz;
            for (int kc = 0; kc < 32; kc++) {
                const float4* brz = g_C1rz + kc * 64;
                ulonglong2 w01 = *(const ulonglong2*)(brz + jcC);
                ulonglong2 w23 = *(const ulonglong2*)(brz + 32 + jcC);
                u64 W[4] = {w01.x, w01.y, w23.x, w23.y};
#pragma unroll
                for (int c = 0; c < 4; c++) {
                    const u64* hA = h1d + (4 * kc + c) * 8 + r0C;
                    ulonglong2 hx = *(const ulonglong2*)(hA + 0);
                    ulonglong2 hy = *(const ulonglong2*)(hA + 2);
                    acc[0] = fma2(W[c], hx.x, acc[0]);
                    acc[1] = fma2(W[c], hx.y, acc[1]);
                    acc[2] = fma2(W[c], hy.x, acc[2]);
                    acc[3] = fma2(W[c], hy.y, acc[3]);
                }
            }
            for (int kc = 0; kc < 8; kc++) {
                const float4* brz = g_C2rz + kc * 64;
                ulonglong2 w01 = *(const ulonglong2*)(brz + jcC);
                ulonglong2 w23 = *(const ulonglong2*)(brz + 32 + jcC);
                u64 W[4] = {w01.x, w01.y, w23.x, w23.y};
#pragma unroll
                for (int c = 0; c < 4; c++) {
                    const u64* hA = h2d + (4 * kc + c) * 8 + r0C;
                    ulonglong2 hx = *(const ulonglong2*)(hA + 0);
                    ulonglong2 hy = *(const ulonglong2*)(hA + 2);
                    acc[0] = fma2(W[c], hx.x, acc[0]);
                    acc[1] = fma2(W[c], hx.y, acc[1]);
                    acc[2] = fma2(W[c], hy.x, acc[2]);
                    acc[3] = fma2(W[c], hy.y, acc[3]);
                }
            }
#pragma unroll
            for (int i = 0; i < 4; i++) cmb[(r0C + i) * 32 + jcC] = acc[i];
        } else if (tid < 128) {
            u64 acc[4];
#pragma unroll
            for (int i = 0; i < 4; i++) acc[i] = bCin;
            for (int kc = 0; kc < 32; kc++) {
                float4 wn4 = g_C1n[kc * 32 + jcC];
                u64 W[4] = {pk2(wn4.x, wn4.x), pk2(wn4.y, wn4.y),
                            pk2(wn4.z, wn4.z), pk2(wn4.w, wn4.w)};
#pragma unroll
                for (int c = 0; c < 4; c++) {
                    const u64* hA = h1d + (4 * kc + c) * 8 + r0C;
                    ulonglong2 hx = *(const ulonglong2*)(hA + 0);
                    ulonglong2 hy = *(const ulonglong2*)(hA + 2);
                    acc[0] = fma2(W[c], hx.x, acc[0]);
                    acc[1] = fma2(W[c], hx.y, acc[1]);
                    acc[2] = fma2(W[c], hy.x, acc[2]);
                    acc[3] = fma2(W[c], hy.y, acc[3]);
                }
            }
#pragma unroll
            for (int i = 0; i < 4; i++) cmb[256 + (r0C + i) * 32 + jcC] = acc[i];
        }
        __syncthreads();

        // ======== C combine: 256 items ========
        if (tid < 256) {
            int jc = tid & 31, row = tid >> 5;
            u64 rz2 = cmb[row * 32 + jc];
            u64 iN2 = cmb[256 + row * 32 + jc];
            u64 hN2 = cCHN[row * 32 + jc];
            float cr, cz;
            up2(rz2, cr, cz);
            float hold = lo2(h2d[jc * 8 + row]);
            float rg = sigf(cr), zg = sigf(cz);
            float ng = tanh_(lo2(iN2) + rg * lo2(hN2));
            float v = (1.0f - zg) * ng + zg * hold;
            h2d[jc * 8 + row] = pk2(v, v);
        }
        __syncthreads();

        // ======== Phase D: projection ========
        if (tid < BT * Vsz) {
            float acc = bpjD;
#pragma unroll
            for (int k = 0; k < 32; k++)
                acc += g_WprojT[k * Vsz + jD] * lo2(h2d[k * 8 + rowD]);
            out[((size_t)(b0 + rowD) * Ssz + st) * Vsz + jD] = acc;
            lg[rowD * 44 + jD] = acc;
        }
        __syncthreads();

        if (tid < BT && pred) {
            float best = lg[tid * 44];
            int bi = 0;
#pragma unroll 1
            for (int j = 1; j < Vsz; j++) {
                float v = lg[tid * 44 + j];
                if (v > best) { best = v; bi = j; }
            }
            pred[(size_t)(b0 + tid) * Ssz + st] = (float)bi;
        }
    }
}

// ---------------- launch ----------------
extern "C" void kernel_launch(void* const* d_in, const int* in_sizes, int n_in,
                              void* d_out, int out_size) {
    const float* latent  = (const float*)d_in[0];
    const int*   tokens  = (const int*)d_in[1];
    const float* W_emb   = (const float*)d_in[2];
    const float* b_emb   = (const float*)d_in[3];
    const float* W_init  = (const float*)d_in[4];
    const float* b_init  = (const float*)d_in[5];
    const float* Wih0    = (const float*)d_in[6];
    const float* Whh0    = (const float*)d_in[7];
    const float* bih0    = (const float*)d_in[8];
    const float* bhh0    = (const float*)d_in[9];
    const float* Wih1    = (const float*)d_in[10];
    const float* Whh1    = (const float*)d_in[11];
    const float* bih1    = (const float*)d_in[12];
    const float* bhh1    = (const float*)d_in[13];
    const float* Wih2    = (const float*)d_in[14];
    const float* Whh2    = (const float*)d_in[15];
    const float* bih2    = (const float*)d_in[16];
    const float* bhh2    = (const float*)d_in[17];
    const float* W_proj  = (const float*)d_in[18];
    const float* b_proj  = (const float*)d_in[19];

    float* out = (float*)d_out;
    size_t logits_elems = (size_t)Bsz * Ssz * Vsz;
    float* pred = ((size_t)out_size >= logits_elems + (size_t)Bsz * Ssz)
                      ? out + logits_elems : nullptr;

    cudaFuncSetAttribute(k_main, cudaFuncAttributeMaxDynamicSharedMemorySize, SM_TOTAL);

    k_prep<<<256, 256>>>(latent, W_emb, b_emb, W_init, b_init, Wih0, bih0, Whh0,
                         Wih1, Whh1, Wih2, Whh2, W_proj);
    k_main<<<NCTA, NTHR, SM_TOTAL>>>(tokens, bhh0, bih1, bhh1, bih2, bhh2, b_proj, out, pred);
}